// round 8
// baseline (speedup 1.0000x reference)
#include <cuda_runtime.h>
#include <cstddef>

// Problem constants (fixed by setup_inputs)
#define B 512
#define L 100
#define M_NEG 10
#define D 256
#define NASP 14

// Output layout: r_s [B,D], z_s [B,D], z_n [B,M,D]
#define R_OFF   0
#define Z_OFF   (B * D)
#define ZN_OFF  (2 * B * D)

struct __align__(16) Smem {
    float  part[8][D];       // per-group/warp partial sums (8 KB)
    float4 yv4[D / 4];       // y_s, later reused for z_s (1 KB)
    float4 My4[D / 4];       // M_w @ y_s + b (1 KB)
    float  wts[16];          // aspect logits
    float  red[32];
    int    sidx[128];
};

struct F8 { float f[8]; };

// 256-bit gather load with L2 evict_last (E_w stays resident in L2).
__device__ __forceinline__ F8 ldg_el8(const float* p) {
    F8 v;
    asm volatile("ld.global.L2::evict_last.v8.b32 {%0,%1,%2,%3,%4,%5,%6,%7}, [%8];"
                 : "=f"(v.f[0]), "=f"(v.f[1]), "=f"(v.f[2]), "=f"(v.f[3]),
                   "=f"(v.f[4]), "=f"(v.f[5]), "=f"(v.f[6]), "=f"(v.f[7])
                 : "l"(p));
    return v;
}
// Streaming store for outputs (don't pollute L2).
__device__ __forceinline__ void st_cs(float* p, float v) {
    asm volatile("st.global.cs.f32 [%0], %1;" :: "l"(p), "f"(v));
}

__device__ __forceinline__ float block_reduce_sum_256(float v, float* red) {
    #pragma unroll
    for (int o = 16; o > 0; o >>= 1) v += __shfl_down_sync(0xffffffffu, v, o);
    const int w = threadIdx.x >> 5, lane = threadIdx.x & 31;
    if (lane == 0) red[w] = v;
    __syncthreads();
    if (w == 0) {
        v = (lane < 8) ? red[lane] : 0.f;
        #pragma unroll
        for (int o = 4; o > 0; o >>= 1) v += __shfl_down_sync(0xffffffffu, v, o);
        if (lane == 0) red[0] = v;
    }
    __syncthreads();
    float r = red[0];
    __syncthreads();
    return r;
}

// Group-cooperative unweighted row-sum gather (phase 1 / neg path).
// Group g = tid>>5 (one warp), lane q = tid&31 owns dims [8q, 8q+8).
// One warp pulls a full 1KB row per LDG.256. Rows l = g, g+8, ...
__device__ __forceinline__ float group_gather_sum8(
    const float* __restrict__ E_w, Smem& sm)
{
    const int tid = threadIdx.x;
    const int g = tid >> 5, q = tid & 31;

    float acc[8];
    #pragma unroll
    for (int i = 0; i < 8; i++) acc[i] = 0.f;

    #pragma unroll 4
    for (int l = g; l < L; l += 8) {
        F8 e = ldg_el8(E_w + ((size_t)sm.sidx[l] << 8) + 8 * q);
        #pragma unroll
        for (int i = 0; i < 8; i++) acc[i] += e.f[i];
    }

    float4* dst = reinterpret_cast<float4*>(sm.part[g] + 8 * q);
    dst[0] = make_float4(acc[0], acc[1], acc[2], acc[3]);
    dst[1] = make_float4(acc[4], acc[5], acc[6], acc[7]);
    __syncthreads();

    float s = 0.f;
    #pragma unroll
    for (int w8 = 0; w8 < 8; w8++) s += sm.part[w8][tid];
    __syncthreads();   // part[] reusable afterwards
    return s;
}

__device__ __forceinline__ float dot8_shfl(float4 a0, float4 b0, float4 a1, float4 b1) {
    float s = a0.x * b0.x + a0.y * b0.y + a0.z * b0.z + a0.w * b0.w
            + a1.x * b1.x + a1.y * b1.y + a1.z * b1.z + a1.w * b1.w;
    #pragma unroll
    for (int o = 16; o > 0; o >>= 1) s += __shfl_down_sync(0xffffffffu, s, o);
    return s;
}

// ---------------------------------------------------------------------------
// Fat kernel: blocks [0, B) = pos path, blocks [B, B + B*M) = neg path.
// ---------------------------------------------------------------------------
extern "C" __global__ void __launch_bounds__(256, 8)
abae_fat_kernel(const int* __restrict__ pos,
                const int* __restrict__ negs,
                const float* __restrict__ E_w,
                const float* __restrict__ T_w,
                const float* __restrict__ M_w,
                const float* __restrict__ M_b,
                const float* __restrict__ lin_w,
                const float* __restrict__ lin_b,
                float* __restrict__ out)
{
    __shared__ Smem sm;
    const int tid = threadIdx.x;
    const int wid = tid >> 5, lane = tid & 31;

    if (blockIdx.x >= B) {
        // ---------------- NEG PATH:  z_n = l2norm(mean_L E_w[negs]) --------
        const int bm = blockIdx.x - B;
        if (tid < L) sm.sidx[tid] = negs[(size_t)bm * L + tid];
        __syncthreads();

        float s = group_gather_sum8(E_w, sm);
        float ss = block_reduce_sum_256(s * s, sm.red);
        float nm  = sqrtf(ss) * (1.0f / (float)L);
        float inv = (1.0f / (float)L) / fmaxf(nm, 1e-12f);
        st_cs(out + ZN_OFF + (size_t)bm * D + tid, s * inv);
        return;
    }

    // ------------------------- POS PATH --------------------------------
    const int b = blockIdx.x;
    float* yv  = reinterpret_cast<float*>(sm.yv4);
    float* Myf = reinterpret_cast<float*>(sm.My4);

    if (tid < L) sm.sidx[tid] = pos[(size_t)b * L + tid];
    __syncthreads();

    // Phase 1: y_s = mean_L e
    float ysum = group_gather_sum8(E_w, sm);
    yv[tid] = ysum * (1.0f / (float)L);
    __syncthreads();

    // Phase 2: My = M_w @ y_s + M_b   (warp-cooperative, float4 rows)
    for (int j = wid; j < D; j += 8) {
        const float4* mrow = reinterpret_cast<const float4*>(M_w + (size_t)j * D);
        float s = dot8_shfl(mrow[lane], sm.yv4[lane],
                            mrow[lane + 32], sm.yv4[lane + 32]);
        if (lane == 0) Myf[j] = s + M_b[j];
    }
    __syncthreads();

    // Phase 3+4 FUSED: one pass over rows. Warp wid owns rows l = wid, wid+8...
    // Lane loads its full 8-float row slice with ONE 256-bit load:
    // dot -> shfl-reduce -> weight -> accumulate. My re-read from smem each
    // iter (LDS cheap) to stay under the 32-reg cap.
    // (global softmax denominator cancels in the l2norm)
    {
        float acc[8];
        #pragma unroll
        for (int i = 0; i < 8; i++) acc[i] = 0.f;

        const float4* My4p = reinterpret_cast<const float4*>(Myf);
        for (int l = wid; l < L; l += 8) {
            F8 e = ldg_el8(E_w + ((size_t)sm.sidx[l] << 8) + 8 * lane);
            float4 m0 = My4p[2 * lane];
            float4 m1 = My4p[2 * lane + 1];
            float s = e.f[0] * m0.x + e.f[1] * m0.y + e.f[2] * m0.z + e.f[3] * m0.w
                    + e.f[4] * m1.x + e.f[5] * m1.y + e.f[6] * m1.z + e.f[7] * m1.w;
            #pragma unroll
            for (int o = 16; o > 0; o >>= 1) s += __shfl_xor_sync(0xffffffffu, s, o);
            float w = __expf(tanhf(s));
            #pragma unroll
            for (int i = 0; i < 8; i++) acc[i] = fmaf(w, e.f[i], acc[i]);
        }
        float4* dst = reinterpret_cast<float4*>(sm.part[wid] + 8 * lane);
        dst[0] = make_float4(acc[0], acc[1], acc[2], acc[3]);
        dst[1] = make_float4(acc[4], acc[5], acc[6], acc[7]);
    }
    __syncthreads();

    float v = 0.f;
    #pragma unroll
    for (int w8 = 0; w8 < 8; w8++) v += sm.part[w8][tid];

    float ss = block_reduce_sum_256(v * v, sm.red);
    float z  = v / fmaxf(sqrtf(ss), 1e-12f);
    st_cs(out + Z_OFF + (size_t)b * D + tid, z);

    __syncthreads();
    yv[tid] = z;                 // stash z_s (yv no longer read)
    __syncthreads();

    // Phase 5: logits[a] = dot(z, lin_w[a]) + lin_b[a]  (warp-per-aspect)
    for (int a = wid; a < NASP; a += 8) {
        const float4* lr = reinterpret_cast<const float4*>(lin_w + (size_t)a * D);
        float s = dot8_shfl(lr[lane], sm.yv4[lane],
                            lr[lane + 32], sm.yv4[lane + 32]);
        if (lane == 0) sm.wts[a] = s + lin_b[a];
    }
    __syncthreads();

    // Phase 6: softmax over 14 aspects folded into T_w combine, then l2norm
    float mx = -1e30f;
    #pragma unroll
    for (int a = 0; a < NASP; a++) mx = fmaxf(mx, sm.wts[a]);
    float psum = 0.f, r = 0.f;
    #pragma unroll
    for (int a = 0; a < NASP; a++) {
        float p = __expf(sm.wts[a] - mx);
        psum += p;
        r = fmaf(p, T_w[a * D + tid], r);
    }
    r /= psum;

    float rss = block_reduce_sum_256(r * r, sm.red);
    st_cs(out + R_OFF + (size_t)b * D + tid, r / fmaxf(sqrtf(rss), 1e-12f));
}

// ---------------------------------------------------------------------------
// Inputs (metadata order): pos, negs, E_w, T_w, M_w, M_b, lin_w, lin_b
// ---------------------------------------------------------------------------
extern "C" void kernel_launch(void* const* d_in, const int* in_sizes, int n_in,
                              void* d_out, int out_size)
{
    const int*   pos   = (const int*)  d_in[0];
    const int*   negs  = (const int*)  d_in[1];
    const float* E_w   = (const float*)d_in[2];
    const float* T_w   = (const float*)d_in[3];
    const float* M_w   = (const float*)d_in[4];
    const float* M_b   = (const float*)d_in[5];
    const float* lin_w = (const float*)d_in[6];
    const float* lin_b = (const float*)d_in[7];
    float* out = (float*)d_out;

    abae_fat_kernel<<<B + B * M_NEG, 256>>>(pos, negs, E_w, T_w, M_w, M_b,
                                            lin_w, lin_b, out);
}

// round 10
// speedup vs baseline: 1.1154x; 1.1154x over previous
#include <cuda_runtime.h>
#include <cstddef>

// Problem constants (fixed by setup_inputs)
#define B 512
#define L 100
#define M_NEG 10
#define D 256
#define NASP 14

// Output layout: r_s [B,D], z_s [B,D], z_n [B,M,D]
#define R_OFF   0
#define Z_OFF   (B * D)
#define ZN_OFF  (2 * B * D)

struct __align__(16) Smem {
    float4 part[8][D / 4];   // per-warp partial sums (8 KB)
    float4 yv4[D / 4];       // y_s, later reused for z_s (1 KB)
    float4 My4[D / 4];       // M_w @ y_s + b (1 KB)
    float  wts[16];          // aspect logits
    float  red[32];
    int    sidx[128];
};

// Streaming store for outputs (don't pollute L2).
__device__ __forceinline__ void st_cs(float* p, float v) {
    asm volatile("st.global.cs.f32 [%0], %1;" :: "l"(p), "f"(v));
}

__device__ __forceinline__ float block_reduce_sum_256(float v, float* red) {
    #pragma unroll
    for (int o = 16; o > 0; o >>= 1) v += __shfl_down_sync(0xffffffffu, v, o);
    const int w = threadIdx.x >> 5, lane = threadIdx.x & 31;
    if (lane == 0) red[w] = v;
    __syncthreads();
    if (w == 0) {
        v = (lane < 8) ? red[lane] : 0.f;
        #pragma unroll
        for (int o = 4; o > 0; o >>= 1) v += __shfl_down_sync(0xffffffffu, v, o);
        if (lane == 0) red[0] = v;
    }
    __syncthreads();
    float r = red[0];
    __syncthreads();
    return r;
}

__device__ __forceinline__ void fma4(float4& a, float w, const float4& v) {
    a.x = fmaf(w, v.x, a.x);
    a.y = fmaf(w, v.y, a.y);
    a.z = fmaf(w, v.z, a.z);
    a.w = fmaf(w, v.w, a.w);
}

// Group-cooperative unweighted row-sum gather (phase 1 / neg path).
// thread (g = tid>>6, q = tid&63) owns dims [4q,4q+4), rows l = g, g+4, ...
// Two independent load/FMA chains for MLP.  (R3-proven layout.)
__device__ __forceinline__ float group_gather_sum(
    const float* __restrict__ E_w, Smem& sm)
{
    const int tid = threadIdx.x;
    const int g = tid >> 6, q = tid & 63;
    const float4* __restrict__ Ev = reinterpret_cast<const float4*>(E_w);

    float4 acc0 = make_float4(0.f, 0.f, 0.f, 0.f);
    float4 acc1 = make_float4(0.f, 0.f, 0.f, 0.f);

    int l = g;
    #pragma unroll
    for (int k = 0; k < 12; k++) {          // 12 pairs = rows g..g+92
        float4 v0 = Ev[((size_t)sm.sidx[l]     << 6) + q];
        float4 v1 = Ev[((size_t)sm.sidx[l + 4] << 6) + q];
        fma4(acc0, 1.0f, v0);
        fma4(acc1, 1.0f, v1);
        l += 8;
    }
    {                                        // remainder row g+96
        float4 v0 = Ev[((size_t)sm.sidx[l] << 6) + q];
        fma4(acc0, 1.0f, v0);
    }
    acc0.x += acc1.x; acc0.y += acc1.y; acc0.z += acc1.z; acc0.w += acc1.w;

    sm.part[g][q] = acc0;
    __syncthreads();
    const float* p = reinterpret_cast<const float*>(sm.part);
    float s = p[0 * D + tid] + p[1 * D + tid] + p[2 * D + tid] + p[3 * D + tid];
    __syncthreads();   // part[] reusable afterwards
    return s;
}

__device__ __forceinline__ float dot8_shfl(float4 a0, float4 b0, float4 a1, float4 b1) {
    float s = a0.x * b0.x + a0.y * b0.y + a0.z * b0.z + a0.w * b0.w
            + a1.x * b1.x + a1.y * b1.y + a1.z * b1.z + a1.w * b1.w;
    #pragma unroll
    for (int o = 16; o > 0; o >>= 1) s += __shfl_down_sync(0xffffffffu, s, o);
    return s;
}

// ---------------------------------------------------------------------------
// Fat kernel: blocks [0, B) = pos path, blocks [B, B + B*M) = neg path.
// ---------------------------------------------------------------------------
extern "C" __global__ void __launch_bounds__(256, 8)
abae_fat_kernel(const int* __restrict__ pos,
                const int* __restrict__ negs,
                const float* __restrict__ E_w,
                const float* __restrict__ T_w,
                const float* __restrict__ M_w,
                const float* __restrict__ M_b,
                const float* __restrict__ lin_w,
                const float* __restrict__ lin_b,
                float* __restrict__ out)
{
    __shared__ Smem sm;
    const int tid = threadIdx.x;
    const int wid = tid >> 5, lane = tid & 31;

    if (blockIdx.x >= B) {
        // ---------------- NEG PATH:  z_n = l2norm(mean_L E_w[negs]) --------
        const int bm = blockIdx.x - B;
        if (tid < L) sm.sidx[tid] = negs[(size_t)bm * L + tid];
        __syncthreads();

        float s = group_gather_sum(E_w, sm);
        float ss = block_reduce_sum_256(s * s, sm.red);
        float nm  = sqrtf(ss) * (1.0f / (float)L);
        float inv = (1.0f / (float)L) / fmaxf(nm, 1e-12f);
        st_cs(out + ZN_OFF + (size_t)bm * D + tid, s * inv);
        return;
    }

    // ------------------------- POS PATH --------------------------------
    const int b = blockIdx.x;
    const float4* __restrict__ Ev = reinterpret_cast<const float4*>(E_w);
    float* yv  = reinterpret_cast<float*>(sm.yv4);
    float* Myf = reinterpret_cast<float*>(sm.My4);

    if (tid < L) sm.sidx[tid] = pos[(size_t)b * L + tid];
    __syncthreads();

    // Phase 1: y_s = mean_L e
    float ysum = group_gather_sum(E_w, sm);
    yv[tid] = ysum * (1.0f / (float)L);
    __syncthreads();

    // Phase 2: My = M_w @ y_s + M_b   (warp-cooperative, float4 rows)
    for (int j = wid; j < D; j += 8) {
        const float4* mrow = reinterpret_cast<const float4*>(M_w + (size_t)j * D);
        float s = dot8_shfl(mrow[lane], sm.yv4[lane],
                            mrow[lane + 32], sm.yv4[lane + 32]);
        if (lane == 0) Myf[j] = s + M_b[j];
    }
    __syncthreads();

    // Phase 3+4 FUSED: one pass over rows. Warp wid owns rows l = wid, wid+8...
    // Lane keeps its 8-float row slice (two float4 loads) in regs:
    // dot -> shfl-reduce -> weight -> accumulate.
    // (global softmax denominator cancels in the l2norm)
    {
        float4 acc0 = make_float4(0.f, 0.f, 0.f, 0.f);
        float4 acc1 = make_float4(0.f, 0.f, 0.f, 0.f);
        const float4 m0 = sm.My4[lane];
        const float4 m1 = sm.My4[lane + 32];
        for (int l = wid; l < L; l += 8) {
            const float4* row = Ev + ((size_t)sm.sidx[l] << 6);
            float4 e0 = row[lane];
            float4 e1 = row[lane + 32];
            float s = e0.x * m0.x + e0.y * m0.y + e0.z * m0.z + e0.w * m0.w
                    + e1.x * m1.x + e1.y * m1.y + e1.z * m1.z + e1.w * m1.w;
            #pragma unroll
            for (int o = 16; o > 0; o >>= 1) s += __shfl_xor_sync(0xffffffffu, s, o);
            float w = __expf(tanhf(s));
            fma4(acc0, w, e0);
            fma4(acc1, w, e1);
        }
        sm.part[wid][lane]      = acc0;   // dims [4*lane, 4*lane+4)
        sm.part[wid][lane + 32] = acc1;   // dims [128+4*lane, ...)
    }
    __syncthreads();

    float v = 0.f;
    {
        const float* p = reinterpret_cast<const float*>(sm.part);
        #pragma unroll
        for (int w8 = 0; w8 < 8; w8++) v += p[w8 * D + tid];
    }
    float ss = block_reduce_sum_256(v * v, sm.red);
    float z  = v / fmaxf(sqrtf(ss), 1e-12f);
    st_cs(out + Z_OFF + (size_t)b * D + tid, z);

    __syncthreads();
    yv[tid] = z;                 // stash z_s (yv no longer read)
    __syncthreads();

    // Phase 5: logits[a] = dot(z, lin_w[a]) + lin_b[a]  (warp-per-aspect)
    for (int a = wid; a < NASP; a += 8) {
        const float4* lr = reinterpret_cast<const float4*>(lin_w + (size_t)a * D);
        float s = dot8_shfl(lr[lane], sm.yv4[lane],
                            lr[lane + 32], sm.yv4[lane + 32]);
        if (lane == 0) sm.wts[a] = s + lin_b[a];
    }
    __syncthreads();

    // Phase 6: softmax over 14 aspects folded into T_w combine, then l2norm
    float mx = -1e30f;
    #pragma unroll
    for (int a = 0; a < NASP; a++) mx = fmaxf(mx, sm.wts[a]);
    float psum = 0.f, r = 0.f;
    #pragma unroll
    for (int a = 0; a < NASP; a++) {
        float p = __expf(sm.wts[a] - mx);
        psum += p;
        r = fmaf(p, T_w[a * D + tid], r);
    }
    r /= psum;

    float rss = block_reduce_sum_256(r * r, sm.red);
    st_cs(out + R_OFF + (size_t)b * D + tid, r / fmaxf(sqrtf(rss), 1e-12f));
}

// ---------------------------------------------------------------------------
// Inputs (metadata order): pos, negs, E_w, T_w, M_w, M_b, lin_w, lin_b
// ---------------------------------------------------------------------------
extern "C" void kernel_launch(void* const* d_in, const int* in_sizes, int n_in,
                              void* d_out, int out_size)
{
    const int*   pos   = (const int*)  d_in[0];
    const int*   negs  = (const int*)  d_in[1];
    const float* E_w   = (const float*)d_in[2];
    const float* T_w   = (const float*)d_in[3];
    const float* M_w   = (const float*)d_in[4];
    const float* M_b   = (const float*)d_in[5];
    const float* lin_w = (const float*)d_in[6];
    const float* lin_b = (const float*)d_in[7];
    float* out = (float*)d_out;

    abae_fat_kernel<<<B + B * M_NEG, 256>>>(pos, negs, E_w, T_w, M_w, M_b,
                                            lin_w, lin_b, out);
}